// round 1
// baseline (speedup 1.0000x reference)
#include <cuda_runtime.h>
#include <float.h>
#include <limits.h>

// Problem constants
#define N 8192
#define D 1024

// GEMM tiling
#define BM 128
#define BN 128
#define BK 16
#define TM 8
#define TN 8
#define NTHREADS 256
#define JSPLIT 4
#define JCHUNK (N / JSPLIT)   // 2048 columns per CTA slice

// Scratch (allocation-free rule: __device__ globals)
__device__ float g_n2[N];
__device__ float g_pval[JSPLIT * N];
__device__ int   g_pidx[JSPLIT * N];
__device__ int   g_idx[N];

// ---------------------------------------------------------------------------
// 1) n2[j] = sum_d negative[j][d]^2   (one warp per row)
// ---------------------------------------------------------------------------
__global__ void n2_kernel(const float* __restrict__ B) {
    int row  = blockIdx.x * 8 + (threadIdx.x >> 5);
    int lane = threadIdx.x & 31;
    const float4* p = reinterpret_cast<const float4*>(B + (size_t)row * D);
    float s = 0.f;
#pragma unroll
    for (int it = 0; it < (D / 4) / 32; ++it) {   // 8 iterations
        float4 v = p[it * 32 + lane];
        s += v.x * v.x + v.y * v.y + v.z * v.z + v.w * v.w;
    }
#pragma unroll
    for (int off = 16; off > 0; off >>= 1)
        s += __shfl_xor_sync(0xFFFFFFFFu, s, off);
    if (lane == 0) g_n2[row] = s;
}

// ---------------------------------------------------------------------------
// 2) Fused fp32 GEMM + running row-argmax over a j-slice.
//    score(i,j) = n2[j] - 2 * dot(a_i, n_j)  (argmax-equivalent to MSE)
// ---------------------------------------------------------------------------
__global__ void __launch_bounds__(NTHREADS, 2)
gemm_argmax_kernel(const float* __restrict__ A, const float* __restrict__ B) {
    const int itile  = blockIdx.x;            // 0..63
    const int jsplit = blockIdx.y;            // 0..JSPLIT-1
    const int i0 = itile * BM;

    __shared__ float As[BK][BM];               // transposed A tile
    __shared__ float Bs[BK][BN];               // transposed B tile
    __shared__ float rval[BM][16];
    __shared__ int   ridx[BM][16];

    const int tid = threadIdx.x;
    const int tx  = tid & 15;                  // column group (0..15)
    const int ty  = tid >> 4;                  // row group (0..15)

    // gmem -> smem loading indices: each thread loads 2 float4 per matrix
    const int lrow = tid >> 2;                 // 0..63
    const int lk4  = (tid & 3) << 2;           // 0,4,8,12

    float best[TM];
    int   bidx[TM];
#pragma unroll
    for (int m = 0; m < TM; ++m) { best[m] = -FLT_MAX; bidx[m] = INT_MAX; }

    for (int jt = 0; jt < JCHUNK / BN; ++jt) {
        const int j0 = jsplit * JCHUNK + jt * BN;

        float acc[TM][TN];
#pragma unroll
        for (int m = 0; m < TM; ++m)
#pragma unroll
            for (int n = 0; n < TN; ++n) acc[m][n] = 0.f;

        for (int kt = 0; kt < D; kt += BK) {
            // load tiles (coalesced float4 along k), store transposed
            float4 a0 = *reinterpret_cast<const float4*>(&A[(size_t)(i0 + lrow)      * D + kt + lk4]);
            float4 a1 = *reinterpret_cast<const float4*>(&A[(size_t)(i0 + lrow + 64) * D + kt + lk4]);
            float4 b0 = *reinterpret_cast<const float4*>(&B[(size_t)(j0 + lrow)      * D + kt + lk4]);
            float4 b1 = *reinterpret_cast<const float4*>(&B[(size_t)(j0 + lrow + 64) * D + kt + lk4]);

            __syncthreads();   // previous tile fully consumed
            As[lk4 + 0][lrow] = a0.x;  As[lk4 + 1][lrow] = a0.y;
            As[lk4 + 2][lrow] = a0.z;  As[lk4 + 3][lrow] = a0.w;
            As[lk4 + 0][lrow + 64] = a1.x;  As[lk4 + 1][lrow + 64] = a1.y;
            As[lk4 + 2][lrow + 64] = a1.z;  As[lk4 + 3][lrow + 64] = a1.w;
            Bs[lk4 + 0][lrow] = b0.x;  Bs[lk4 + 1][lrow] = b0.y;
            Bs[lk4 + 2][lrow] = b0.z;  Bs[lk4 + 3][lrow] = b0.w;
            Bs[lk4 + 0][lrow + 64] = b1.x;  Bs[lk4 + 1][lrow + 64] = b1.y;
            Bs[lk4 + 2][lrow + 64] = b1.z;  Bs[lk4 + 3][lrow + 64] = b1.w;
            __syncthreads();

#pragma unroll
            for (int k = 0; k < BK; ++k) {
                float a[TM], b[TN];
                float4 av0 = *reinterpret_cast<const float4*>(&As[k][ty * TM]);
                float4 av1 = *reinterpret_cast<const float4*>(&As[k][ty * TM + 4]);
                float4 bv0 = *reinterpret_cast<const float4*>(&Bs[k][tx * TN]);
                float4 bv1 = *reinterpret_cast<const float4*>(&Bs[k][tx * TN + 4]);
                a[0] = av0.x; a[1] = av0.y; a[2] = av0.z; a[3] = av0.w;
                a[4] = av1.x; a[5] = av1.y; a[6] = av1.z; a[7] = av1.w;
                b[0] = bv0.x; b[1] = bv0.y; b[2] = bv0.z; b[3] = bv0.w;
                b[4] = bv1.x; b[5] = bv1.y; b[6] = bv1.z; b[7] = bv1.w;
#pragma unroll
                for (int m = 0; m < TM; ++m)
#pragma unroll
                    for (int n = 0; n < TN; ++n)
                        acc[m][n] = fmaf(a[m], b[n], acc[m][n]);
            }
        }

        // fold this tile into the running argmax (ascending n => ascending j:
        // strict '>' preserves first-max semantics within a thread)
#pragma unroll
        for (int n = 0; n < TN; ++n) {
            const int j = j0 + tx * TN + n;
            const float n2v = g_n2[j];
#pragma unroll
            for (int m = 0; m < TM; ++m) {
                float s = n2v - 2.0f * acc[m][n];
                if (s > best[m]) { best[m] = s; bidx[m] = j; }
            }
        }
    }

    // cross-thread (tx) reduction per row with min-idx tie-break
    __syncthreads();
#pragma unroll
    for (int m = 0; m < TM; ++m) {
        rval[ty * TM + m][tx] = best[m];
        ridx[ty * TM + m][tx] = bidx[m];
    }
    __syncthreads();
    if (tid < BM) {
        float bv = -FLT_MAX;
        int   bi = INT_MAX;
#pragma unroll
        for (int t = 0; t < 16; ++t) {
            float v = rval[tid][t];
            int   i = ridx[tid][t];
            if (v > bv || (v == bv && i < bi)) { bv = v; bi = i; }
        }
        g_pval[jsplit * N + i0 + tid] = bv;
        g_pidx[jsplit * N + i0 + tid] = bi;
    }
}

// ---------------------------------------------------------------------------
// 3) Reduce JSPLIT partials per row (ascending slice = ascending j, so strict
//    '>' keeps the first max; equal values prefer smaller idx).
// ---------------------------------------------------------------------------
__global__ void reduce_kernel() {
    int i = blockIdx.x * blockDim.x + threadIdx.x;
    float bv = -FLT_MAX;
    int   bi = INT_MAX;
#pragma unroll
    for (int s = 0; s < JSPLIT; ++s) {
        float v = g_pval[s * N + i];
        int   x = g_pidx[s * N + i];
        if (v > bv || (v == bv && x < bi)) { bv = v; bi = x; }
    }
    g_idx[i] = bi;
}

// ---------------------------------------------------------------------------
// 4) Gather: out[i] = negative[g_idx[i]]
// ---------------------------------------------------------------------------
__global__ void gather_kernel(const float* __restrict__ B, float* __restrict__ out) {
    int i = blockIdx.x;
    int j = g_idx[i];
    const float4* src = reinterpret_cast<const float4*>(B + (size_t)j * D);
    float4* dst = reinterpret_cast<float4*>(out + (size_t)i * D);
    dst[threadIdx.x] = src[threadIdx.x];   // 256 threads * float4 = 1024 floats
}

// ---------------------------------------------------------------------------
extern "C" void kernel_launch(void* const* d_in, const int* in_sizes, int n_in,
                              void* d_out, int out_size) {
    const float* anchor   = (const float*)d_in[0];
    const float* negative = (const float*)d_in[1];
    float* out = (float*)d_out;

    n2_kernel<<<N / 8, 256>>>(negative);
    gemm_argmax_kernel<<<dim3(N / BM, JSPLIT), NTHREADS>>>(anchor, negative);
    reduce_kernel<<<N / 256, 256>>>();
    gather_kernel<<<N, D / 4 / 1>>>(negative, out);
}

// round 3
// speedup vs baseline: 3.4568x; 3.4568x over previous
#include <cuda_runtime.h>
#include <cuda_fp16.h>
#include <cstdint>
#include <float.h>

// ---------------------------------------------------------------------------
#define N 8192
#define D 1024
#define BM 128
#define BN 128
#define BK 32
#define NJT (N / BN)          // 64 j-tiles
#define EPS 8.0f              // candidate margin (error bound ~4.2)

// __device__ globals (allocation-free rule)
__device__ float  g_n2[N];
__device__ float  g_At[(size_t)N * D];     // tf32-rounded anchor  (32 MB)
__device__ float  g_Bt[(size_t)N * D];     // tf32-rounded negative(32 MB)
__device__ __half g_S[(size_t)N * N];      // approx scores (128 MB)
__device__ float  g_tmax[(size_t)N * NJT]; // per (row, j-tile) max (2 MB)
__device__ float  g_rowmax[N];

// ---------------------------------------------------------------------------
__device__ __forceinline__ uint32_t smem_u32(const void* p) {
    uint32_t a;
    asm("{ .reg .u64 t; cvta.to.shared.u64 t, %1; cvt.u32.u64 %0, t; }" : "=r"(a) : "l"(p));
    return a;
}
__device__ __forceinline__ void cp_async16(uint32_t saddr, const void* gaddr) {
    asm volatile("cp.async.cg.shared.global [%0], [%1], 16;" :: "r"(saddr), "l"(gaddr));
}
#define CP_COMMIT()  asm volatile("cp.async.commit_group;" ::: "memory")
#define CP_WAIT(nn)  asm volatile("cp.async.wait_group %0;" :: "n"(nn) : "memory")

__device__ __forceinline__ void mma_tf32(float* d, const uint32_t* a, const uint32_t* b) {
    asm volatile(
        "mma.sync.aligned.m16n8k8.row.col.f32.tf32.tf32.f32 "
        "{%0,%1,%2,%3}, {%4,%5,%6,%7}, {%8,%9}, {%0,%1,%2,%3};"
        : "+f"(d[0]), "+f"(d[1]), "+f"(d[2]), "+f"(d[3])
        : "r"(a[0]), "r"(a[1]), "r"(a[2]), "r"(a[3]), "r"(b[0]), "r"(b[1]));
}

// ---------------------------------------------------------------------------
// n2[j] = ||negative_j||^2 exact fp32
__global__ void n2_kernel(const float* __restrict__ B) {
    int row  = blockIdx.x * 8 + (threadIdx.x >> 5);
    int lane = threadIdx.x & 31;
    const float4* p = reinterpret_cast<const float4*>(B + (size_t)row * D);
    float s = 0.f;
#pragma unroll
    for (int it = 0; it < (D / 4) / 32; ++it) {
        float4 v = p[it * 32 + lane];
        s += v.x * v.x + v.y * v.y + v.z * v.z + v.w * v.w;
    }
#pragma unroll
    for (int off = 16; off > 0; off >>= 1) s += __shfl_xor_sync(0xFFFFFFFFu, s, off);
    if (lane == 0) g_n2[row] = s;
}

// tf32 (round-to-nearest) pre-conversion
__global__ void cvt_kernel(const float* __restrict__ src, float* __restrict__ dst) {
    size_t idx = ((size_t)blockIdx.x * 256 + threadIdx.x) * 4;
    float4 v = *reinterpret_cast<const float4*>(src + idx);
    uint32_t r0, r1, r2, r3;
    asm("cvt.rna.tf32.f32 %0, %1;" : "=r"(r0) : "f"(v.x));
    asm("cvt.rna.tf32.f32 %0, %1;" : "=r"(r1) : "f"(v.y));
    asm("cvt.rna.tf32.f32 %0, %1;" : "=r"(r2) : "f"(v.z));
    asm("cvt.rna.tf32.f32 %0, %1;" : "=r"(r3) : "f"(v.w));
    float4 o = make_float4(__uint_as_float(r0), __uint_as_float(r1),
                           __uint_as_float(r2), __uint_as_float(r3));
    *reinterpret_cast<float4*>(dst + idx) = o;
}

// ---------------------------------------------------------------------------
// Phase 1: tf32 mma.sync GEMM tile (128x128, K=1024).
// score = n2[j] - 2*dot. Writes fp16 scores + per-row tile max (fp32).
// ---------------------------------------------------------------------------
// smem float layout:
//   A stages: [0 .. 2*5120)     (stage stride 5120 floats = 128 rows * 40)
//   B stages: [10240 .. 20480)
//   n2s:      [20480 .. 20608)
//   tmaxs:    [20608 .. 21120)  (128 rows x 4 n-warps)
#define SM_FLOATS 21120
#define ROWSTRIDE 40

__global__ void __launch_bounds__(256, 2)
gemm_kernel() {
    extern __shared__ float sm[];
    const uint32_t sb = smem_u32(sm);
    const int tid  = threadIdx.x;
    const int lane = tid & 31;
    const int wid  = tid >> 5;
    const int wm   = wid >> 2;       // 0..1
    const int wn   = wid & 3;        // 0..3
    const int g    = lane >> 2;      // 0..7
    const int tig  = lane & 3;       // 0..3

    const int it = blockIdx.x, jt = blockIdx.y;
    const int i0 = it * BM, j0 = jt * BN;

    float* n2s   = sm + 20480;
    float* tmaxs = sm + 20608;
    if (tid < BN) n2s[tid] = g_n2[j0 + tid];

    // loader indices: 8 threads per 32-float row, 4 rows-groups per thread
    const int lr = tid >> 3;         // 0..31
    const int lc = (tid & 7) * 4;    // 0,4,...,28

    const float* Ag = g_At + (size_t)i0 * D;
    const float* Bg = g_Bt + (size_t)j0 * D;

    // issue chunk into stage st
    auto issue = [&](int c, int st) {
        uint32_t sa = sb + (uint32_t)(st * 5120) * 4;
        uint32_t sbb = sb + (uint32_t)(10240 + st * 5120) * 4;
        const float* ag = Ag + c * BK;
        const float* bg = Bg + c * BK;
#pragma unroll
        for (int v = 0; v < 4; ++v) {
            int r = lr + v * 32;
            cp_async16(sa  + (uint32_t)(r * ROWSTRIDE + lc) * 4, ag + (size_t)r * D + lc);
            cp_async16(sbb + (uint32_t)(r * ROWSTRIDE + lc) * 4, bg + (size_t)r * D + lc);
        }
        CP_COMMIT();
    };

    issue(0, 0);
    issue(1, 1);

    float acc[4][4][4];
#pragma unroll
    for (int m = 0; m < 4; ++m)
#pragma unroll
        for (int n = 0; n < 4; ++n)
#pragma unroll
            for (int q = 0; q < 4; ++q) acc[m][n][q] = 0.f;

    const int NCH = D / BK;   // 32
    for (int c = 0; c < NCH; ++c) {
        const int st = c & 1;
        if (c == NCH - 1) CP_WAIT(0); else CP_WAIT(1);
        __syncthreads();

        const float* As_ = sm + st * 5120 + (wm * 64) * ROWSTRIDE;
        const float* Bs_ = sm + 10240 + st * 5120 + (wn * 32) * ROWSTRIDE;
#pragma unroll
        for (int ks = 0; ks < 4; ++ks) {
            const int k0 = ks * 8;
            uint32_t a[4][4], b[4][2];
#pragma unroll
            for (int mt = 0; mt < 4; ++mt) {
                int base = (mt * 16 + g) * ROWSTRIDE + k0 + tig;
                a[mt][0] = __float_as_uint(As_[base]);
                a[mt][1] = __float_as_uint(As_[base + 8 * ROWSTRIDE]);
                a[mt][2] = __float_as_uint(As_[base + 4]);
                a[mt][3] = __float_as_uint(As_[base + 8 * ROWSTRIDE + 4]);
            }
#pragma unroll
            for (int nt = 0; nt < 4; ++nt) {
                int base = (nt * 8 + g) * ROWSTRIDE + k0 + tig;
                b[nt][0] = __float_as_uint(Bs_[base]);
                b[nt][1] = __float_as_uint(Bs_[base + 4]);
            }
#pragma unroll
            for (int mt = 0; mt < 4; ++mt)
#pragma unroll
                for (int nt = 0; nt < 4; ++nt)
                    mma_tf32(acc[mt][nt], a[mt], b[nt]);
        }
        __syncthreads();
        if (c + 2 < NCH) issue(c + 2, st);
    }

    // Epilogue: scores, fp16 store, per-row max
    float rmax[8];
#pragma unroll
    for (int q = 0; q < 8; ++q) rmax[q] = -FLT_MAX;

#pragma unroll
    for (int mt = 0; mt < 4; ++mt) {
        const int r0 = wm * 64 + mt * 16 + g;
        const int r1 = r0 + 8;
#pragma unroll
        for (int nt = 0; nt < 4; ++nt) {
            const int c0 = wn * 32 + nt * 8 + tig * 2;
            float s00 = n2s[c0]     - 2.f * acc[mt][nt][0];
            float s01 = n2s[c0 + 1] - 2.f * acc[mt][nt][1];
            float s10 = n2s[c0]     - 2.f * acc[mt][nt][2];
            float s11 = n2s[c0 + 1] - 2.f * acc[mt][nt][3];
            *reinterpret_cast<__half2*>(&g_S[(size_t)(i0 + r0) * N + j0 + c0]) =
                __floats2half2_rn(s00, s01);
            *reinterpret_cast<__half2*>(&g_S[(size_t)(i0 + r1) * N + j0 + c0]) =
                __floats2half2_rn(s10, s11);
            rmax[mt * 2]     = fmaxf(rmax[mt * 2],     fmaxf(s00, s01));
            rmax[mt * 2 + 1] = fmaxf(rmax[mt * 2 + 1], fmaxf(s10, s11));
        }
    }
    // reduce across the 4 lanes that share a row (tig dimension)
#pragma unroll
    for (int q = 0; q < 8; ++q) {
        rmax[q] = fmaxf(rmax[q], __shfl_xor_sync(0xFFFFFFFFu, rmax[q], 1));
        rmax[q] = fmaxf(rmax[q], __shfl_xor_sync(0xFFFFFFFFu, rmax[q], 2));
    }
    if (tig == 0) {
#pragma unroll
        for (int mt = 0; mt < 4; ++mt) {
            tmaxs[(wm * 64 + mt * 16 + g) * 4 + wn]     = rmax[mt * 2];
            tmaxs[(wm * 64 + mt * 16 + g + 8) * 4 + wn] = rmax[mt * 2 + 1];
        }
    }
    __syncthreads();
    if (tid < BM) {
        float m = fmaxf(fmaxf(tmaxs[tid * 4 + 0], tmaxs[tid * 4 + 1]),
                        fmaxf(tmaxs[tid * 4 + 2], tmaxs[tid * 4 + 3]));
        g_tmax[(size_t)(i0 + tid) * NJT + jt] = m;
    }
}

// ---------------------------------------------------------------------------
__global__ void rowmax_kernel() {
    int row  = blockIdx.x * 8 + (threadIdx.x >> 5);
    int lane = threadIdx.x & 31;
    float m = fmaxf(g_tmax[(size_t)row * NJT + lane],
                    g_tmax[(size_t)row * NJT + 32 + lane]);
#pragma unroll
    for (int off = 16; off > 0; off >>= 1)
        m = fmaxf(m, __shfl_xor_sync(0xFFFFFFFFu, m, off));
    if (lane == 0) g_rowmax[row] = m;
}

// ---------------------------------------------------------------------------
// Phase 3: per-row candidate scan + exact fp32 rescore + gather. 1 CTA/row.
// ---------------------------------------------------------------------------
__global__ void __launch_bounds__(256)
select_kernel(const float* __restrict__ A, const float* __restrict__ B,
              float* __restrict__ out) {
    const int i = blockIdx.x;
    const int tid = threadIdx.x, lane = tid & 31, wid = tid >> 5;

    __shared__ int   cnt;
    __shared__ int   cand[128];
    __shared__ float wred[8];
    __shared__ int   bestj_s;

    const float thresh = g_rowmax[i] - EPS;
    const float4 a4 = reinterpret_cast<const float4*>(A + (size_t)i * D)[tid];

    if (tid == 0) cnt = 0;
    __syncthreads();

    const __half* srow = g_S + (size_t)i * N;
    for (int j = tid; j < N; j += 256) {
        if (__half2float(srow[j]) > thresh) {
            int p = atomicAdd(&cnt, 1);
            if (p < 128) cand[p] = j;
        }
    }
    __syncthreads();
    const int nc = min(cnt, 128);

    float bestv = -FLT_MAX;
    int   bestj = 0x7fffffff;
    for (int c = 0; c < nc; ++c) {
        const int j = cand[c];
        const float4 b4 = reinterpret_cast<const float4*>(B + (size_t)j * D)[tid];
        float p = a4.x * b4.x + a4.y * b4.y + a4.z * b4.z + a4.w * b4.w;
#pragma unroll
        for (int off = 16; off > 0; off >>= 1) p += __shfl_xor_sync(0xFFFFFFFFu, p, off);
        if (lane == 0) wred[wid] = p;
        __syncthreads();
        if (tid == 0) {
            float dot = wred[0] + wred[1] + wred[2] + wred[3]
                      + wred[4] + wred[5] + wred[6] + wred[7];
            float sc = g_n2[j] - 2.f * dot;
            if (sc > bestv || (sc == bestv && j < bestj)) { bestv = sc; bestj = j; }
        }
        __syncthreads();
    }
    if (tid == 0) bestj_s = bestj;
    __syncthreads();

    const int j = bestj_s;
    reinterpret_cast<float4*>(out + (size_t)i * D)[tid] =
        reinterpret_cast<const float4*>(B + (size_t)j * D)[tid];
}

// ---------------------------------------------------------------------------
extern "C" void kernel_launch(void* const* d_in, const int* in_sizes, int n_in,
                              void* d_out, int out_size) {
    const float* anchor   = (const float*)d_in[0];
    const float* negative = (const float*)d_in[1];
    float* out = (float*)d_out;

    static float* s_At = nullptr;
    static float* s_Bt = nullptr;
    if (!s_At) { cudaGetSymbolAddress((void**)&s_At, g_At);
                 cudaGetSymbolAddress((void**)&s_Bt, g_Bt); }

    cudaFuncSetAttribute(gemm_kernel,
                         cudaFuncAttributeMaxDynamicSharedMemorySize,
                         SM_FLOATS * 4);

    n2_kernel<<<N / 8, 256>>>(negative);
    cvt_kernel<<<(int)(((size_t)N * D) / 1024), 256>>>(anchor,   s_At);
    cvt_kernel<<<(int)(((size_t)N * D) / 1024), 256>>>(negative, s_Bt);
    gemm_kernel<<<dim3(N / BM, N / BN), 256, SM_FLOATS * 4>>>();
    rowmax_kernel<<<N / 8, 256>>>();
    select_kernel<<<N, 256>>>(anchor, negative, out);
}

// round 4
// speedup vs baseline: 6.2862x; 1.8185x over previous
#include <cuda_runtime.h>
#include <cuda_fp16.h>
#include <cuda_bf16.h>
#include <cstdint>
#include <float.h>

// ---------------------------------------------------------------------------
#define N 8192
#define D 1024
#define BM 128
#define BN 128
#define BK 32                 // bf16 elems per chunk (64 B/row)
#define NJT (N / BN)          // 64 j-tiles
#define EPS 20.0f             // candidate margin (worst-case bf16+fp16 err ~13.2)
#define STAGES 4
#define MAXC 256              // candidate buffer per row

// __device__ globals (allocation-free rule)
__device__ float          g_n2[N];
__device__ __nv_bfloat16  g_Ah[(size_t)N * D];   // 16 MB
__device__ __nv_bfloat16  g_Bh[(size_t)N * D];   // 16 MB
__device__ __half         g_S[(size_t)N * N];    // approx scores (128 MB)
__device__ float          g_tmax[(size_t)N * NJT];
__device__ float          g_rowmax[N];

// ---------------------------------------------------------------------------
__device__ __forceinline__ uint32_t smem_u32(const void* p) {
    uint32_t a;
    asm("{ .reg .u64 t; cvta.to.shared.u64 t, %1; cvt.u32.u64 %0, t; }" : "=r"(a) : "l"(p));
    return a;
}
__device__ __forceinline__ void cp_async16(uint32_t saddr, const void* gaddr) {
    asm volatile("cp.async.cg.shared.global [%0], [%1], 16;" :: "r"(saddr), "l"(gaddr));
}
#define CP_COMMIT()  asm volatile("cp.async.commit_group;" ::: "memory")
#define CP_WAIT(nn)  asm volatile("cp.async.wait_group %0;" :: "n"(nn) : "memory")

__device__ __forceinline__ void mma_bf16(float* d, const uint32_t* a, const uint32_t* b) {
    asm volatile(
        "mma.sync.aligned.m16n8k16.row.col.f32.bf16.bf16.f32 "
        "{%0,%1,%2,%3}, {%4,%5,%6,%7}, {%8,%9}, {%0,%1,%2,%3};"
        : "+f"(d[0]), "+f"(d[1]), "+f"(d[2]), "+f"(d[3])
        : "r"(a[0]), "r"(a[1]), "r"(a[2]), "r"(a[3]), "r"(b[0]), "r"(b[1]));
}

// ---------------------------------------------------------------------------
// n2[j] = ||negative_j||^2 exact fp32
__global__ void n2_kernel(const float* __restrict__ B) {
    int row  = blockIdx.x * 8 + (threadIdx.x >> 5);
    int lane = threadIdx.x & 31;
    const float4* p = reinterpret_cast<const float4*>(B + (size_t)row * D);
    float s = 0.f;
#pragma unroll
    for (int it = 0; it < (D / 4) / 32; ++it) {
        float4 v = p[it * 32 + lane];
        s += v.x * v.x + v.y * v.y + v.z * v.z + v.w * v.w;
    }
#pragma unroll
    for (int off = 16; off > 0; off >>= 1) s += __shfl_xor_sync(0xFFFFFFFFu, s, off);
    if (lane == 0) g_n2[row] = s;
}

// fp32 -> bf16 (rn)
__global__ void cvt_kernel(const float* __restrict__ src, __nv_bfloat16* __restrict__ dst) {
    size_t idx = ((size_t)blockIdx.x * 256 + threadIdx.x) * 4;
    float4 v = *reinterpret_cast<const float4*>(src + idx);
    __nv_bfloat162 lo = __floats2bfloat162_rn(v.x, v.y);
    __nv_bfloat162 hi = __floats2bfloat162_rn(v.z, v.w);
    uint2 o = make_uint2(*reinterpret_cast<uint32_t*>(&lo), *reinterpret_cast<uint32_t*>(&hi));
    *reinterpret_cast<uint2*>(dst + idx) = o;
}

// ---------------------------------------------------------------------------
// Phase 1: bf16 mma.sync GEMM tile (128x128, K=1024), 4-stage cp.async.
// score = n2[j] - 2*dot. Writes fp16 scores + per-(row,tile) fp32 max.
// smem (bytes):
//   A stages: [0 .. STAGES*10240)            (stage = 128 rows * 80 B)
//   B stages: [40960 .. 81920)
//   n2s:      [81920 .. 82432)   (128 f32)
//   tmaxs:    [82432 .. 84480)   (128*4 f32)
// ---------------------------------------------------------------------------
#define STG_BYTES 10240
#define ROWB 80                      // bytes per smem row (20 words: conflict-free)
#define SM_B_OFF  (STAGES * STG_BYTES)
#define SM_N2_OFF (2 * STAGES * STG_BYTES)
#define SM_TM_OFF (SM_N2_OFF + 512)
#define SM_TOTAL  (SM_TM_OFF + 2048)

__global__ void __launch_bounds__(256, 2)
gemm_kernel() {
    extern __shared__ __align__(16) char sm[];
    const uint32_t sb = smem_u32(sm);
    const int tid  = threadIdx.x;
    const int lane = tid & 31;
    const int wid  = tid >> 5;
    const int wm   = wid >> 2;       // 0..1
    const int wn   = wid & 3;        // 0..3
    const int g    = lane >> 2;      // 0..7
    const int tig  = lane & 3;       // 0..3

    const int it = blockIdx.x, jt = blockIdx.y;
    const int i0 = it * BM, j0 = jt * BN;

    float* n2s   = reinterpret_cast<float*>(sm + SM_N2_OFF);
    float* tmaxs = reinterpret_cast<float*>(sm + SM_TM_OFF);
    if (tid < BN) n2s[tid] = g_n2[j0 + tid];

    // loader: 4 threads per 64-B row; each thread 16 B; 2 row-waves per matrix
    const int lr = tid >> 2;               // 0..63
    const int lcb = (tid & 3) * 16;        // byte col: 0,16,32,48

    const __nv_bfloat16* Ag = g_Ah + (size_t)i0 * D;
    const __nv_bfloat16* Bg = g_Bh + (size_t)j0 * D;

    auto issue = [&](int c) {              // no commit inside
        const int st = ((unsigned)c) % STAGES;
        uint32_t sa = sb + st * STG_BYTES;
        uint32_t sbb = sb + SM_B_OFF + st * STG_BYTES;
        const char* ag = reinterpret_cast<const char*>(Ag + c * BK);
        const char* bg = reinterpret_cast<const char*>(Bg + c * BK);
#pragma unroll
        for (int v = 0; v < 2; ++v) {
            int r = lr + v * 64;
            cp_async16(sa  + (uint32_t)(r * ROWB + lcb), ag + (size_t)r * (D * 2) + lcb);
            cp_async16(sbb + (uint32_t)(r * ROWB + lcb), bg + (size_t)r * (D * 2) + lcb);
        }
    };

    issue(0); CP_COMMIT();
    issue(1); CP_COMMIT();
    issue(2); CP_COMMIT();

    float acc[4][4][4];
#pragma unroll
    for (int m = 0; m < 4; ++m)
#pragma unroll
        for (int n = 0; n < 4; ++n)
#pragma unroll
            for (int q = 0; q < 4; ++q) acc[m][n][q] = 0.f;

    const int NCH = D / BK;   // 32
    for (int c = 0; c < NCH; ++c) {
        const int st = ((unsigned)c) % STAGES;
        CP_WAIT(2);
        __syncthreads();

        const char* As_ = sm + st * STG_BYTES + (wm * 64) * ROWB;
        const char* Bs_ = sm + SM_B_OFF + st * STG_BYTES + (wn * 32) * ROWB;
#pragma unroll
        for (int ks = 0; ks < BK / 16; ++ks) {      // 2
            const int kb = ks * 32 + tig * 4;       // byte offset of this lane's pair
            uint32_t a[4][4], b[4][2];
#pragma unroll
            for (int mt = 0; mt < 4; ++mt) {
                const char* base = As_ + (mt * 16 + g) * ROWB + kb;
                a[mt][0] = *reinterpret_cast<const uint32_t*>(base);
                a[mt][1] = *reinterpret_cast<const uint32_t*>(base + 8 * ROWB);
                a[mt][2] = *reinterpret_cast<const uint32_t*>(base + 16);
                a[mt][3] = *reinterpret_cast<const uint32_t*>(base + 8 * ROWB + 16);
            }
#pragma unroll
            for (int nt = 0; nt < 4; ++nt) {
                const char* base = Bs_ + (nt * 8 + g) * ROWB + kb;
                b[nt][0] = *reinterpret_cast<const uint32_t*>(base);
                b[nt][1] = *reinterpret_cast<const uint32_t*>(base + 16);
            }
#pragma unroll
            for (int mt = 0; mt < 4; ++mt)
#pragma unroll
                for (int nt = 0; nt < 4; ++nt)
                    mma_bf16(acc[mt][nt], a[mt], b[nt]);
        }
        __syncthreads();
        if (c + 3 < NCH) issue(c + 3);
        CP_COMMIT();                                 // keep group count aligned
    }

    // Epilogue: scores, fp16 store, per-row max
    float rmax[8];
#pragma unroll
    for (int q = 0; q < 8; ++q) rmax[q] = -FLT_MAX;

#pragma unroll
    for (int mt = 0; mt < 4; ++mt) {
        const int r0 = wm * 64 + mt * 16 + g;
        const int r1 = r0 + 8;
#pragma unroll
        for (int nt = 0; nt < 4; ++nt) {
            const int c0 = wn * 32 + nt * 8 + tig * 2;
            float s00 = n2s[c0]     - 2.f * acc[mt][nt][0];
            float s01 = n2s[c0 + 1] - 2.f * acc[mt][nt][1];
            float s10 = n2s[c0]     - 2.f * acc[mt][nt][2];
            float s11 = n2s[c0 + 1] - 2.f * acc[mt][nt][3];
            *reinterpret_cast<__half2*>(&g_S[(size_t)(i0 + r0) * N + j0 + c0]) =
                __floats2half2_rn(s00, s01);
            *reinterpret_cast<__half2*>(&g_S[(size_t)(i0 + r1) * N + j0 + c0]) =
                __floats2half2_rn(s10, s11);
            rmax[mt * 2]     = fmaxf(rmax[mt * 2],     fmaxf(s00, s01));
            rmax[mt * 2 + 1] = fmaxf(rmax[mt * 2 + 1], fmaxf(s10, s11));
        }
    }
#pragma unroll
    for (int q = 0; q < 8; ++q) {
        rmax[q] = fmaxf(rmax[q], __shfl_xor_sync(0xFFFFFFFFu, rmax[q], 1));
        rmax[q] = fmaxf(rmax[q], __shfl_xor_sync(0xFFFFFFFFu, rmax[q], 2));
    }
    if (tig == 0) {
#pragma unroll
        for (int mt = 0; mt < 4; ++mt) {
            tmaxs[(wm * 64 + mt * 16 + g) * 4 + wn]     = rmax[mt * 2];
            tmaxs[(wm * 64 + mt * 16 + g + 8) * 4 + wn] = rmax[mt * 2 + 1];
        }
    }
    __syncthreads();
    if (tid < BM) {
        float m = fmaxf(fmaxf(tmaxs[tid * 4 + 0], tmaxs[tid * 4 + 1]),
                        fmaxf(tmaxs[tid * 4 + 2], tmaxs[tid * 4 + 3]));
        g_tmax[(size_t)(i0 + tid) * NJT + jt] = m;
    }
}

// ---------------------------------------------------------------------------
__global__ void rowmax_kernel() {
    int row  = blockIdx.x * 8 + (threadIdx.x >> 5);
    int lane = threadIdx.x & 31;
    float m = fmaxf(g_tmax[(size_t)row * NJT + lane],
                    g_tmax[(size_t)row * NJT + 32 + lane]);
#pragma unroll
    for (int off = 16; off > 0; off >>= 1)
        m = fmaxf(m, __shfl_xor_sync(0xFFFFFFFFu, m, off));
    if (lane == 0) g_rowmax[row] = m;
}

// ---------------------------------------------------------------------------
// Phase 3: per-row candidate scan + exact fp32 rescore + gather. 1 CTA/row.
// ---------------------------------------------------------------------------
__global__ void __launch_bounds__(256)
select_kernel(const float* __restrict__ A, const float* __restrict__ B,
              float* __restrict__ out) {
    const int i = blockIdx.x;
    const int tid = threadIdx.x, lane = tid & 31, wid = tid >> 5;

    __shared__ int   cnt;
    __shared__ int   cand[MAXC];
    __shared__ float wred[8];
    __shared__ int   bestj_s;

    const float thresh = g_rowmax[i] - EPS;
    const float4 a4 = reinterpret_cast<const float4*>(A + (size_t)i * D)[tid];

    if (tid == 0) cnt = 0;
    __syncthreads();

    const __half* srow = g_S + (size_t)i * N;
    for (int j = tid; j < N; j += 256) {
        if (__half2float(srow[j]) > thresh) {
            int p = atomicAdd(&cnt, 1);
            if (p < MAXC) cand[p] = j;
        }
    }
    __syncthreads();
    const int nc = min(cnt, MAXC);

    float bestv = -FLT_MAX;
    int   bestj = 0x7fffffff;
    for (int c = 0; c < nc; ++c) {
        const int j = cand[c];
        const float4 b4 = reinterpret_cast<const float4*>(B + (size_t)j * D)[tid];
        float p = a4.x * b4.x + a4.y * b4.y + a4.z * b4.z + a4.w * b4.w;
#pragma unroll
        for (int off = 16; off > 0; off >>= 1) p += __shfl_xor_sync(0xFFFFFFFFu, p, off);
        if (lane == 0) wred[wid] = p;
        __syncthreads();
        if (tid == 0) {
            float dot = wred[0] + wred[1] + wred[2] + wred[3]
                      + wred[4] + wred[5] + wred[6] + wred[7];
            float sc = g_n2[j] - 2.f * dot;
            if (sc > bestv || (sc == bestv && j < bestj)) { bestv = sc; bestj = j; }
        }
        __syncthreads();
    }
    if (tid == 0) bestj_s = bestj;
    __syncthreads();

    const int j = bestj_s;
    reinterpret_cast<float4*>(out + (size_t)i * D)[tid] =
        reinterpret_cast<const float4*>(B + (size_t)j * D)[tid];
}

// ---------------------------------------------------------------------------
extern "C" void kernel_launch(void* const* d_in, const int* in_sizes, int n_in,
                              void* d_out, int out_size) {
    const float* anchor   = (const float*)d_in[0];
    const float* negative = (const float*)d_in[1];
    float* out = (float*)d_out;

    static __nv_bfloat16* s_Ah = nullptr;
    static __nv_bfloat16* s_Bh = nullptr;
    if (!s_Ah) { cudaGetSymbolAddress((void**)&s_Ah, g_Ah);
                 cudaGetSymbolAddress((void**)&s_Bh, g_Bh); }

    cudaFuncSetAttribute(gemm_kernel,
                         cudaFuncAttributeMaxDynamicSharedMemorySize, SM_TOTAL);

    n2_kernel<<<N / 8, 256>>>(negative);
    cvt_kernel<<<(int)(((size_t)N * D) / 1024), 256>>>(anchor,   s_Ah);
    cvt_kernel<<<(int)(((size_t)N * D) / 1024), 256>>>(negative, s_Bh);
    gemm_kernel<<<dim3(N / BM, N / BN), 256, SM_TOTAL>>>();
    rowmax_kernel<<<N / 8, 256>>>();
    select_kernel<<<N, 256>>>(anchor, negative, out);
}

// round 5
// speedup vs baseline: 6.9650x; 1.1080x over previous
#include <cuda_runtime.h>
#include <cuda_fp16.h>
#include <cuda_bf16.h>
#include <cstdint>
#include <float.h>

// ---------------------------------------------------------------------------
#define N 8192
#define D 1024
#define BM 128
#define BN 128
#define BK 32                 // bf16 elems per chunk (64 B/row)
#define NJT (N / BN)          // 64 j-tiles
#define EPS 20.0f             // candidate margin (worst-case bf16+fp16 err ~13.2)
#define STAGES 4
#define MAXC 256              // candidate buffer per row

// __device__ globals (allocation-free rule)
__device__ float          g_n2[N];
__device__ __nv_bfloat16  g_Ah[(size_t)N * D];   // 16 MB
__device__ __nv_bfloat16  g_Bh[(size_t)N * D];   // 16 MB
__device__ __half         g_S[(size_t)N * N];    // approx scores (128 MB)
__device__ float          g_tmax[(size_t)N * NJT];
__device__ float          g_rowmax[N];

// ---------------------------------------------------------------------------
__device__ __forceinline__ uint32_t smem_u32(const void* p) {
    uint32_t a;
    asm("{ .reg .u64 t; cvta.to.shared.u64 t, %1; cvt.u32.u64 %0, t; }" : "=r"(a) : "l"(p));
    return a;
}
__device__ __forceinline__ void cp_async16(uint32_t saddr, const void* gaddr) {
    asm volatile("cp.async.cg.shared.global [%0], [%1], 16;" :: "r"(saddr), "l"(gaddr));
}
#define CP_COMMIT()  asm volatile("cp.async.commit_group;" ::: "memory")
#define CP_WAIT(nn)  asm volatile("cp.async.wait_group %0;" :: "n"(nn) : "memory")

__device__ __forceinline__ void mma_bf16(float* d, const uint32_t* a, const uint32_t* b) {
    asm volatile(
        "mma.sync.aligned.m16n8k16.row.col.f32.bf16.bf16.f32 "
        "{%0,%1,%2,%3}, {%4,%5,%6,%7}, {%8,%9}, {%0,%1,%2,%3};"
        : "+f"(d[0]), "+f"(d[1]), "+f"(d[2]), "+f"(d[3])
        : "r"(a[0]), "r"(a[1]), "r"(a[2]), "r"(a[3]), "r"(b[0]), "r"(b[1]));
}
__device__ __forceinline__ void ldsm_x4(uint32_t* r, uint32_t addr) {
    asm volatile("ldmatrix.sync.aligned.m8n8.x4.shared.b16 {%0,%1,%2,%3}, [%4];"
        : "=r"(r[0]), "=r"(r[1]), "=r"(r[2]), "=r"(r[3]) : "r"(addr));
}

// ---------------------------------------------------------------------------
// n2[j] = ||negative_j||^2 exact fp32
__global__ void n2_kernel(const float* __restrict__ B) {
    int row  = blockIdx.x * 8 + (threadIdx.x >> 5);
    int lane = threadIdx.x & 31;
    const float4* p = reinterpret_cast<const float4*>(B + (size_t)row * D);
    float s = 0.f;
#pragma unroll
    for (int it = 0; it < (D / 4) / 32; ++it) {
        float4 v = p[it * 32 + lane];
        s += v.x * v.x + v.y * v.y + v.z * v.z + v.w * v.w;
    }
#pragma unroll
    for (int off = 16; off > 0; off >>= 1) s += __shfl_xor_sync(0xFFFFFFFFu, s, off);
    if (lane == 0) g_n2[row] = s;
}

// fp32 -> bf16 (rn)
__global__ void cvt_kernel(const float* __restrict__ src, __nv_bfloat16* __restrict__ dst) {
    size_t idx = ((size_t)blockIdx.x * 256 + threadIdx.x) * 4;
    float4 v = *reinterpret_cast<const float4*>(src + idx);
    __nv_bfloat162 lo = __floats2bfloat162_rn(v.x, v.y);
    __nv_bfloat162 hi = __floats2bfloat162_rn(v.z, v.w);
    uint2 o = make_uint2(*reinterpret_cast<uint32_t*>(&lo), *reinterpret_cast<uint32_t*>(&hi));
    *reinterpret_cast<uint2*>(dst + idx) = o;
}

// ---------------------------------------------------------------------------
// Phase 1: bf16 mma.sync GEMM (128x128, K=1024), 4-stage cp.async + ldmatrix.
// score = n2[j] - 2*dot. Writes fp16 scores + per-(row,tile) fp32 max.
// ---------------------------------------------------------------------------
#define STG_BYTES 10240
#define ROWB 80                      // bytes per smem row (20 words: conflict-free)
#define SM_B_OFF  (STAGES * STG_BYTES)
#define SM_N2_OFF (2 * STAGES * STG_BYTES)
#define SM_TM_OFF (SM_N2_OFF + 512)
#define SM_TOTAL  (SM_TM_OFF + 2048)

__global__ void __launch_bounds__(256, 2)
gemm_kernel() {
    extern __shared__ __align__(16) char sm[];
    const uint32_t sb = smem_u32(sm);
    const int tid  = threadIdx.x;
    const int lane = tid & 31;
    const int wid  = tid >> 5;
    const int wm   = wid >> 2;       // 0..1
    const int wn   = wid & 3;        // 0..3
    const int g    = lane >> 2;      // 0..7
    const int tig  = lane & 3;       // 0..3

    const int it = blockIdx.x, jt = blockIdx.y;
    const int i0 = it * BM, j0 = jt * BN;

    float* n2s   = reinterpret_cast<float*>(sm + SM_N2_OFF);
    float* tmaxs = reinterpret_cast<float*>(sm + SM_TM_OFF);
    if (tid < BN) n2s[tid] = g_n2[j0 + tid];

    // gmem->smem loader: 4 threads per 64-B row, 2 row-waves per matrix
    const int lr = tid >> 2;               // 0..63
    const int lcb = (tid & 3) * 16;        // byte col: 0,16,32,48

    const __nv_bfloat16* Ag = g_Ah + (size_t)i0 * D;
    const __nv_bfloat16* Bg = g_Bh + (size_t)j0 * D;

    auto issue = [&](int c) {              // no commit inside
        const int st = ((unsigned)c) % STAGES;
        uint32_t sa  = sb + st * STG_BYTES;
        uint32_t sbb = sb + SM_B_OFF + st * STG_BYTES;
        const char* ag = reinterpret_cast<const char*>(Ag + c * BK);
        const char* bg = reinterpret_cast<const char*>(Bg + c * BK);
#pragma unroll
        for (int v = 0; v < 2; ++v) {
            int r = lr + v * 64;
            cp_async16(sa  + (uint32_t)(r * ROWB + lcb), ag + (size_t)r * (D * 2) + lcb);
            cp_async16(sbb + (uint32_t)(r * ROWB + lcb), bg + (size_t)r * (D * 2) + lcb);
        }
    };

    issue(0); CP_COMMIT();
    issue(1); CP_COMMIT();
    issue(2); CP_COMMIT();

    // ldmatrix lane offsets (q = lane>>3 selects the 8x8 sub-matrix)
    const int q  = lane >> 3;
    const int r8 = lane & 7;
    const uint32_t aoff = (uint32_t)(((q & 1) * 8 + r8) * ROWB + (q >> 1) * 16);
    const uint32_t boff = (uint32_t)(((q >> 1) * 8 + r8) * ROWB + (q & 1) * 16);

    float acc[4][4][4];
#pragma unroll
    for (int m = 0; m < 4; ++m)
#pragma unroll
        for (int n = 0; n < 4; ++n)
#pragma unroll
            for (int qq = 0; qq < 4; ++qq) acc[m][n][qq] = 0.f;

    const int NCH = D / BK;   // 32
    for (int c = 0; c < NCH; ++c) {
        const int st = ((unsigned)c) % STAGES;
        CP_WAIT(2);
        __syncthreads();
        // stage (c+3)%4 == (c-1)%4 is free after the barrier: issue early
        if (c + 3 < NCH) issue(c + 3);
        CP_COMMIT();

        const uint32_t sA = sb + st * STG_BYTES + (uint32_t)((wm * 64) * ROWB);
        const uint32_t sB = sb + SM_B_OFF + st * STG_BYTES + (uint32_t)((wn * 32) * ROWB);
#pragma unroll
        for (int ks = 0; ks < BK / 16; ++ks) {      // 2
            const uint32_t kb = ks * 32;
            uint32_t a[4][4], b[4][2];
#pragma unroll
            for (int mt = 0; mt < 4; ++mt)
                ldsm_x4(a[mt], sA + (uint32_t)(mt * 16 * ROWB) + kb + aoff);
#pragma unroll
            for (int p = 0; p < 2; ++p) {
                uint32_t bp[4];
                ldsm_x4(bp, sB + (uint32_t)(p * 16 * ROWB) + kb + boff);
                b[2 * p][0]     = bp[0];
                b[2 * p][1]     = bp[1];
                b[2 * p + 1][0] = bp[2];
                b[2 * p + 1][1] = bp[3];
            }
#pragma unroll
            for (int mt = 0; mt < 4; ++mt)
#pragma unroll
                for (int nt = 0; nt < 4; ++nt)
                    mma_bf16(acc[mt][nt], a[mt], b[nt]);
        }
    }

    // Epilogue: scores, fp16 store, per-row max
    __syncthreads();
    float rmax[8];
#pragma unroll
    for (int qq = 0; qq < 8; ++qq) rmax[qq] = -FLT_MAX;

#pragma unroll
    for (int mt = 0; mt < 4; ++mt) {
        const int r0 = wm * 64 + mt * 16 + g;
        const int r1 = r0 + 8;
#pragma unroll
        for (int nt = 0; nt < 4; ++nt) {
            const int c0 = wn * 32 + nt * 8 + tig * 2;
            float s00 = n2s[c0]     - 2.f * acc[mt][nt][0];
            float s01 = n2s[c0 + 1] - 2.f * acc[mt][nt][1];
            float s10 = n2s[c0]     - 2.f * acc[mt][nt][2];
            float s11 = n2s[c0 + 1] - 2.f * acc[mt][nt][3];
            *reinterpret_cast<__half2*>(&g_S[(size_t)(i0 + r0) * N + j0 + c0]) =
                __floats2half2_rn(s00, s01);
            *reinterpret_cast<__half2*>(&g_S[(size_t)(i0 + r1) * N + j0 + c0]) =
                __floats2half2_rn(s10, s11);
            rmax[mt * 2]     = fmaxf(rmax[mt * 2],     fmaxf(s00, s01));
            rmax[mt * 2 + 1] = fmaxf(rmax[mt * 2 + 1], fmaxf(s10, s11));
        }
    }
#pragma unroll
    for (int qq = 0; qq < 8; ++qq) {
        rmax[qq] = fmaxf(rmax[qq], __shfl_xor_sync(0xFFFFFFFFu, rmax[qq], 1));
        rmax[qq] = fmaxf(rmax[qq], __shfl_xor_sync(0xFFFFFFFFu, rmax[qq], 2));
    }
    if (tig == 0) {
#pragma unroll
        for (int mt = 0; mt < 4; ++mt) {
            tmaxs[(wm * 64 + mt * 16 + g) * 4 + wn]     = rmax[mt * 2];
            tmaxs[(wm * 64 + mt * 16 + g + 8) * 4 + wn] = rmax[mt * 2 + 1];
        }
    }
    __syncthreads();
    if (tid < BM) {
        float m = fmaxf(fmaxf(tmaxs[tid * 4 + 0], tmaxs[tid * 4 + 1]),
                        fmaxf(tmaxs[tid * 4 + 2], tmaxs[tid * 4 + 3]));
        g_tmax[(size_t)(i0 + tid) * NJT + jt] = m;
    }
}

// ---------------------------------------------------------------------------
__global__ void rowmax_kernel() {
    int row  = blockIdx.x * 8 + (threadIdx.x >> 5);
    int lane = threadIdx.x & 31;
    float m = fmaxf(g_tmax[(size_t)row * NJT + lane],
                    g_tmax[(size_t)row * NJT + 32 + lane]);
#pragma unroll
    for (int off = 16; off > 0; off >>= 1)
        m = fmaxf(m, __shfl_xor_sync(0xFFFFFFFFu, m, off));
    if (lane == 0) g_rowmax[row] = m;
}

// ---------------------------------------------------------------------------
// Phase 3: per-row candidate scan + exact fp32 rescore + gather. 1 CTA/row.
// ---------------------------------------------------------------------------
__global__ void __launch_bounds__(256)
select_kernel(const float* __restrict__ A, const float* __restrict__ B,
              float* __restrict__ out) {
    const int i = blockIdx.x;
    const int tid = threadIdx.x, lane = tid & 31, wid = tid >> 5;

    __shared__ int   cnt;
    __shared__ int   cand[MAXC];
    __shared__ float wred[8];
    __shared__ int   bestj_s;

    const float thresh = g_rowmax[i] - EPS;
    const float4 a4 = reinterpret_cast<const float4*>(A + (size_t)i * D)[tid];

    if (tid == 0) cnt = 0;
    __syncthreads();

    const __half* srow = g_S + (size_t)i * N;
    for (int j = tid; j < N; j += 256) {
        if (__half2float(srow[j]) > thresh) {
            int p = atomicAdd(&cnt, 1);
            if (p < MAXC) cand[p] = j;
        }
    }
    __syncthreads();
    const int nc = min(cnt, MAXC);

    float bestv = -FLT_MAX;
    int   bestj = 0x7fffffff;
    for (int c = 0; c < nc; ++c) {
        const int j = cand[c];
        const float4 b4 = reinterpret_cast<const float4*>(B + (size_t)j * D)[tid];
        float p = a4.x * b4.x + a4.y * b4.y + a4.z * b4.z + a4.w * b4.w;
#pragma unroll
        for (int off = 16; off > 0; off >>= 1) p += __shfl_xor_sync(0xFFFFFFFFu, p, off);
        if (lane == 0) wred[wid] = p;
        __syncthreads();
        if (tid == 0) {
            float dot = wred[0] + wred[1] + wred[2] + wred[3]
                      + wred[4] + wred[5] + wred[6] + wred[7];
            float sc = g_n2[j] - 2.f * dot;
            if (sc > bestv || (sc == bestv && j < bestj)) { bestv = sc; bestj = j; }
        }
        __syncthreads();
    }
    if (tid == 0) bestj_s = bestj;
    __syncthreads();

    const int j = bestj_s;
    reinterpret_cast<float4*>(out + (size_t)i * D)[tid] =
        reinterpret_cast<const float4*>(B + (size_t)j * D)[tid];
}

// ---------------------------------------------------------------------------
extern "C" void kernel_launch(void* const* d_in, const int* in_sizes, int n_in,
                              void* d_out, int out_size) {
    const float* anchor   = (const float*)d_in[0];
    const float* negative = (const float*)d_in[1];
    float* out = (float*)d_out;

    static __nv_bfloat16* s_Ah = nullptr;
    static __nv_bfloat16* s_Bh = nullptr;
    if (!s_Ah) { cudaGetSymbolAddress((void**)&s_Ah, g_Ah);
                 cudaGetSymbolAddress((void**)&s_Bh, g_Bh); }

    cudaFuncSetAttribute(gemm_kernel,
                         cudaFuncAttributeMaxDynamicSharedMemorySize, SM_TOTAL);

    n2_kernel<<<N / 8, 256>>>(negative);
    cvt_kernel<<<(int)(((size_t)N * D) / 1024), 256>>>(anchor,   s_Ah);
    cvt_kernel<<<(int)(((size_t)N * D) / 1024), 256>>>(negative, s_Bh);
    gemm_kernel<<<dim3(N / BM, N / BN), 256, SM_TOTAL>>>();
    rowmax_kernel<<<N / 8, 256>>>();
    select_kernel<<<N, 256>>>(anchor, negative, out);
}

// round 6
// speedup vs baseline: 7.4920x; 1.0757x over previous
#include <cuda_runtime.h>
#include <cuda_fp16.h>
#include <cuda_bf16.h>
#include <cstdint>
#include <float.h>

// ---------------------------------------------------------------------------
#define N 8192
#define D 1024
#define BM 128
#define BN 128
#define BK 64                 // bf16 elems per chunk (128 B/row)
#define NJT (N / BN)          // 64 j-tiles
#define EPS 20.0f             // candidate margin (worst-case bf16+fp16 err ~13.2)
#define STAGES 2
#define MAXC 256              // candidate buffer per row

// __device__ globals (allocation-free rule)
__device__ float          g_n2[N];
__device__ __nv_bfloat16  g_Ah[(size_t)N * D];   // 16 MB
__device__ __nv_bfloat16  g_Bh[(size_t)N * D];   // 16 MB
__device__ __half         g_S[(size_t)N * N];    // approx scores (128 MB)
__device__ float          g_tmax[(size_t)N * NJT];
__device__ float          g_rowmax[N];

// ---------------------------------------------------------------------------
__device__ __forceinline__ uint32_t smem_u32(const void* p) {
    uint32_t a;
    asm("{ .reg .u64 t; cvta.to.shared.u64 t, %1; cvt.u32.u64 %0, t; }" : "=r"(a) : "l"(p));
    return a;
}
__device__ __forceinline__ void cp_async16(uint32_t saddr, const void* gaddr) {
    asm volatile("cp.async.cg.shared.global [%0], [%1], 16;" :: "r"(saddr), "l"(gaddr));
}
#define CP_COMMIT()  asm volatile("cp.async.commit_group;" ::: "memory")
#define CP_WAIT(nn)  asm volatile("cp.async.wait_group %0;" :: "n"(nn) : "memory")

__device__ __forceinline__ void mma_bf16(float* d, const uint32_t* a, const uint32_t* b) {
    asm volatile(
        "mma.sync.aligned.m16n8k16.row.col.f32.bf16.bf16.f32 "
        "{%0,%1,%2,%3}, {%4,%5,%6,%7}, {%8,%9}, {%0,%1,%2,%3};"
        : "+f"(d[0]), "+f"(d[1]), "+f"(d[2]), "+f"(d[3])
        : "r"(a[0]), "r"(a[1]), "r"(a[2]), "r"(a[3]), "r"(b[0]), "r"(b[1]));
}
__device__ __forceinline__ void ldsm_x4(uint32_t* r, uint32_t addr) {
    asm volatile("ldmatrix.sync.aligned.m8n8.x4.shared.b16 {%0,%1,%2,%3}, [%4];"
        : "=r"(r[0]), "=r"(r[1]), "=r"(r[2]), "=r"(r[3]) : "r"(addr));
}

// ---------------------------------------------------------------------------
// n2[j] = ||negative_j||^2 exact fp32
__global__ void n2_kernel(const float* __restrict__ B) {
    int row  = blockIdx.x * 8 + (threadIdx.x >> 5);
    int lane = threadIdx.x & 31;
    const float4* p = reinterpret_cast<const float4*>(B + (size_t)row * D);
    float s = 0.f;
#pragma unroll
    for (int it = 0; it < (D / 4) / 32; ++it) {
        float4 v = p[it * 32 + lane];
        s += v.x * v.x + v.y * v.y + v.z * v.z + v.w * v.w;
    }
#pragma unroll
    for (int off = 16; off > 0; off >>= 1) s += __shfl_xor_sync(0xFFFFFFFFu, s, off);
    if (lane == 0) g_n2[row] = s;
}

// fp32 -> bf16 (rn)
__global__ void cvt_kernel(const float* __restrict__ src, __nv_bfloat16* __restrict__ dst) {
    size_t idx = ((size_t)blockIdx.x * 256 + threadIdx.x) * 4;
    float4 v = *reinterpret_cast<const float4*>(src + idx);
    __nv_bfloat162 lo = __floats2bfloat162_rn(v.x, v.y);
    __nv_bfloat162 hi = __floats2bfloat162_rn(v.z, v.w);
    uint2 o = make_uint2(*reinterpret_cast<uint32_t*>(&lo), *reinterpret_cast<uint32_t*>(&hi));
    *reinterpret_cast<uint2*>(dst + idx) = o;
}

// ---------------------------------------------------------------------------
// Phase 1: bf16 mma.sync GEMM (128x128, K=1024), BK=64, 2-stage cp.async,
// ldmatrix fragments. score = n2[j] - 2*dot -> fp16 g_S + per-(row,tile) max.
// ---------------------------------------------------------------------------
#define ROWB 144                     // 128 B data + 16 B pad (36 words, bank-clean)
#define STG_BYTES (128 * ROWB)       // 18432
#define SM_B_OFF  (STAGES * STG_BYTES)
#define SM_N2_OFF (2 * STAGES * STG_BYTES)   // 73728
#define SM_TM_OFF (SM_N2_OFF + 512)
#define SM_TOTAL  (SM_TM_OFF + 2048)         // 76288

__global__ void __launch_bounds__(256, 2)
gemm_kernel() {
    extern __shared__ __align__(16) char sm[];
    const uint32_t sb = smem_u32(sm);
    const int tid  = threadIdx.x;
    const int lane = tid & 31;
    const int wid  = tid >> 5;
    const int wm   = wid >> 2;       // 0..1
    const int wn   = wid & 3;        // 0..3
    const int g    = lane >> 2;      // 0..7
    const int tig  = lane & 3;       // 0..3

    const int it = blockIdx.x, jt = blockIdx.y;
    const int i0 = it * BM, j0 = jt * BN;

    float* n2s   = reinterpret_cast<float*>(sm + SM_N2_OFF);
    float* tmaxs = reinterpret_cast<float*>(sm + SM_TM_OFF);
    if (tid < BN) n2s[tid] = g_n2[j0 + tid];

    // gmem->smem loader: 8 threads per 128-B row, 4 row-waves per matrix
    const int lr  = tid >> 3;              // 0..31
    const int lcb = (tid & 7) * 16;        // byte col: 0..112

    const __nv_bfloat16* Ag = g_Ah + (size_t)i0 * D;
    const __nv_bfloat16* Bg = g_Bh + (size_t)j0 * D;

    auto issue = [&](int c) {
        const int st = c & 1;
        uint32_t sa  = sb + st * STG_BYTES;
        uint32_t sbb = sb + SM_B_OFF + st * STG_BYTES;
        const char* ag = reinterpret_cast<const char*>(Ag + c * BK);
        const char* bg = reinterpret_cast<const char*>(Bg + c * BK);
#pragma unroll
        for (int v = 0; v < 4; ++v) {
            int r = lr + v * 32;
            cp_async16(sa  + (uint32_t)(r * ROWB + lcb), ag + (size_t)r * (D * 2) + lcb);
            cp_async16(sbb + (uint32_t)(r * ROWB + lcb), bg + (size_t)r * (D * 2) + lcb);
        }
        CP_COMMIT();
    };

    issue(0);

    // ldmatrix lane offsets (q = lane>>3 selects the 8x8 sub-matrix)
    const int q  = lane >> 3;
    const int r8 = lane & 7;
    const uint32_t aoff = (uint32_t)(((q & 1) * 8 + r8) * ROWB + (q >> 1) * 16);
    const uint32_t boff = (uint32_t)(((q >> 1) * 8 + r8) * ROWB + (q & 1) * 16);

    float acc[4][4][4];
#pragma unroll
    for (int m = 0; m < 4; ++m)
#pragma unroll
        for (int n = 0; n < 4; ++n)
#pragma unroll
            for (int qq = 0; qq < 4; ++qq) acc[m][n][qq] = 0.f;

    const int NCH = D / BK;   // 16
    for (int c = 0; c < NCH; ++c) {
        const int st = c & 1;
        CP_WAIT(0);
        __syncthreads();
        if (c + 1 < NCH) issue(c + 1);   // overlaps this chunk's compute

        const uint32_t sA = sb + st * STG_BYTES + (uint32_t)((wm * 64) * ROWB);
        const uint32_t sB = sb + SM_B_OFF + st * STG_BYTES + (uint32_t)((wn * 32) * ROWB);
#pragma unroll
        for (int ks = 0; ks < BK / 16; ++ks) {      // 4 independent k-slices
            const uint32_t kb = ks * 32;
            uint32_t a[4][4], b[4][2];
#pragma unroll
            for (int mt = 0; mt < 4; ++mt)
                ldsm_x4(a[mt], sA + (uint32_t)(mt * 16 * ROWB) + kb + aoff);
#pragma unroll
            for (int p = 0; p < 2; ++p) {
                uint32_t bp[4];
                ldsm_x4(bp, sB + (uint32_t)(p * 16 * ROWB) + kb + boff);
                b[2 * p][0]     = bp[0];
                b[2 * p][1]     = bp[1];
                b[2 * p + 1][0] = bp[2];
                b[2 * p + 1][1] = bp[3];
            }
#pragma unroll
            for (int mt = 0; mt < 4; ++mt)
#pragma unroll
                for (int nt = 0; nt < 4; ++nt)
                    mma_bf16(acc[mt][nt], a[mt], b[nt]);
        }
    }

    // Epilogue: scores, fp16 store, per-row max
    __syncthreads();
    float rmax[8];
#pragma unroll
    for (int qq = 0; qq < 8; ++qq) rmax[qq] = -FLT_MAX;

#pragma unroll
    for (int mt = 0; mt < 4; ++mt) {
        const int r0 = wm * 64 + mt * 16 + g;
        const int r1 = r0 + 8;
#pragma unroll
        for (int nt = 0; nt < 4; ++nt) {
            const int c0 = wn * 32 + nt * 8 + tig * 2;
            float s00 = n2s[c0]     - 2.f * acc[mt][nt][0];
            float s01 = n2s[c0 + 1] - 2.f * acc[mt][nt][1];
            float s10 = n2s[c0]     - 2.f * acc[mt][nt][2];
            float s11 = n2s[c0 + 1] - 2.f * acc[mt][nt][3];
            *reinterpret_cast<__half2*>(&g_S[(size_t)(i0 + r0) * N + j0 + c0]) =
                __floats2half2_rn(s00, s01);
            *reinterpret_cast<__half2*>(&g_S[(size_t)(i0 + r1) * N + j0 + c0]) =
                __floats2half2_rn(s10, s11);
            rmax[mt * 2]     = fmaxf(rmax[mt * 2],     fmaxf(s00, s01));
            rmax[mt * 2 + 1] = fmaxf(rmax[mt * 2 + 1], fmaxf(s10, s11));
        }
    }
#pragma unroll
    for (int qq = 0; qq < 8; ++qq) {
        rmax[qq] = fmaxf(rmax[qq], __shfl_xor_sync(0xFFFFFFFFu, rmax[qq], 1));
        rmax[qq] = fmaxf(rmax[qq], __shfl_xor_sync(0xFFFFFFFFu, rmax[qq], 2));
    }
    if (tig == 0) {
#pragma unroll
        for (int mt = 0; mt < 4; ++mt) {
            tmaxs[(wm * 64 + mt * 16 + g) * 4 + wn]     = rmax[mt * 2];
            tmaxs[(wm * 64 + mt * 16 + g + 8) * 4 + wn] = rmax[mt * 2 + 1];
        }
    }
    __syncthreads();
    if (tid < BM) {
        float m = fmaxf(fmaxf(tmaxs[tid * 4 + 0], tmaxs[tid * 4 + 1]),
                        fmaxf(tmaxs[tid * 4 + 2], tmaxs[tid * 4 + 3]));
        g_tmax[(size_t)(i0 + tid) * NJT + jt] = m;
    }
}

// ---------------------------------------------------------------------------
__global__ void rowmax_kernel() {
    int row  = blockIdx.x * 8 + (threadIdx.x >> 5);
    int lane = threadIdx.x & 31;
    float m = fmaxf(g_tmax[(size_t)row * NJT + lane],
                    g_tmax[(size_t)row * NJT + 32 + lane]);
#pragma unroll
    for (int off = 16; off > 0; off >>= 1)
        m = fmaxf(m, __shfl_xor_sync(0xFFFFFFFFu, m, off));
    if (lane == 0) g_rowmax[row] = m;
}

// ---------------------------------------------------------------------------
// Phase 3: per-row candidate scan + exact fp32 rescore + gather. 1 CTA/row.
// ---------------------------------------------------------------------------
__global__ void __launch_bounds__(256)
select_kernel(const float* __restrict__ A, const float* __restrict__ B,
              float* __restrict__ out) {
    const int i = blockIdx.x;
    const int tid = threadIdx.x, lane = tid & 31, wid = tid >> 5;

    __shared__ int   cnt;
    __shared__ int   cand[MAXC];
    __shared__ float wred[8];
    __shared__ int   bestj_s;

    const float thresh = g_rowmax[i] - EPS;
    const float4 a4 = reinterpret_cast<const float4*>(A + (size_t)i * D)[tid];

    if (tid == 0) cnt = 0;
    __syncthreads();

    const __half* srow = g_S + (size_t)i * N;
    for (int j = tid; j < N; j += 256) {
        if (__half2float(srow[j]) > thresh) {
            int p = atomicAdd(&cnt, 1);
            if (p < MAXC) cand[p] = j;
        }
    }
    __syncthreads();
    const int nc = min(cnt, MAXC);

    float bestv = -FLT_MAX;
    int   bestj = 0x7fffffff;
    for (int c = 0; c < nc; ++c) {
        const int j = cand[c];
        const float4 b4 = reinterpret_cast<const float4*>(B + (size_t)j * D)[tid];
        float p = a4.x * b4.x + a4.y * b4.y + a4.z * b4.z + a4.w * b4.w;
#pragma unroll
        for (int off = 16; off > 0; off >>= 1) p += __shfl_xor_sync(0xFFFFFFFFu, p, off);
        if (lane == 0) wred[wid] = p;
        __syncthreads();
        if (tid == 0) {
            float dot = wred[0] + wred[1] + wred[2] + wred[3]
                      + wred[4] + wred[5] + wred[6] + wred[7];
            float sc = g_n2[j] - 2.f * dot;
            if (sc > bestv || (sc == bestv && j < bestj)) { bestv = sc; bestj = j; }
        }
        __syncthreads();
    }
    if (tid == 0) bestj_s = bestj;
    __syncthreads();

    const int j = bestj_s;
    reinterpret_cast<float4*>(out + (size_t)i * D)[tid] =
        reinterpret_cast<const float4*>(B + (size_t)j * D)[tid];
}

// ---------------------------------------------------------------------------
extern "C" void kernel_launch(void* const* d_in, const int* in_sizes, int n_in,
                              void* d_out, int out_size) {
    const float* anchor   = (const float*)d_in[0];
    const float* negative = (const float*)d_in[1];
    float* out = (float*)d_out;

    static __nv_bfloat16* s_Ah = nullptr;
    static __nv_bfloat16* s_Bh = nullptr;
    if (!s_Ah) { cudaGetSymbolAddress((void**)&s_Ah, g_Ah);
                 cudaGetSymbolAddress((void**)&s_Bh, g_Bh); }

    cudaFuncSetAttribute(gemm_kernel,
                         cudaFuncAttributeMaxDynamicSharedMemorySize, SM_TOTAL);

    n2_kernel<<<N / 8, 256>>>(negative);
    cvt_kernel<<<(int)(((size_t)N * D) / 1024), 256>>>(anchor,   s_Ah);
    cvt_kernel<<<(int)(((size_t)N * D) / 1024), 256>>>(negative, s_Bh);
    gemm_kernel<<<dim3(N / BM, N / BN), 256, SM_TOTAL>>>();
    rowmax_kernel<<<N / 8, 256>>>();
    select_kernel<<<N, 256>>>(anchor, negative, out);
}

// round 7
// speedup vs baseline: 8.3637x; 1.1163x over previous
#include <cuda_runtime.h>
#include <cuda_fp16.h>
#include <cuda_bf16.h>
#include <cstdint>
#include <float.h>

// ---------------------------------------------------------------------------
#define N 8192
#define D 1024
#define BM 128
#define BN 128
#define BK 64                 // bf16 elems per chunk (128 B/row)
#define NJT (N / BN)          // 64 j-tiles
#define EPS 20.0f             // candidate margin (worst-case bf16+fp16 err ~13.2)
#define STAGES 3
#define MAXC 256              // candidate buffer per row

// __device__ globals (allocation-free rule)
__device__ float          g_n2[N];
__device__ __nv_bfloat16  g_Ah[(size_t)N * D];   // 16 MB
__device__ __nv_bfloat16  g_Bh[(size_t)N * D];   // 16 MB
__device__ __half         g_S[(size_t)N * N];    // approx scores (128 MB)
__device__ float          g_tmax[(size_t)N * NJT];
__device__ float          g_rowmax[N];

// ---------------------------------------------------------------------------
__device__ __forceinline__ uint32_t smem_u32(const void* p) {
    uint32_t a;
    asm("{ .reg .u64 t; cvta.to.shared.u64 t, %1; cvt.u32.u64 %0, t; }" : "=r"(a) : "l"(p));
    return a;
}
__device__ __forceinline__ void cp_async16(uint32_t saddr, const void* gaddr) {
    asm volatile("cp.async.cg.shared.global [%0], [%1], 16;" :: "r"(saddr), "l"(gaddr));
}
#define CP_COMMIT()  asm volatile("cp.async.commit_group;" ::: "memory")
#define CP_WAIT(nn)  asm volatile("cp.async.wait_group %0;" :: "n"(nn) : "memory")

__device__ __forceinline__ void mma_bf16(float* d, const uint32_t* a, const uint32_t* b) {
    asm volatile(
        "mma.sync.aligned.m16n8k16.row.col.f32.bf16.bf16.f32 "
        "{%0,%1,%2,%3}, {%4,%5,%6,%7}, {%8,%9}, {%0,%1,%2,%3};"
        : "+f"(d[0]), "+f"(d[1]), "+f"(d[2]), "+f"(d[3])
        : "r"(a[0]), "r"(a[1]), "r"(a[2]), "r"(a[3]), "r"(b[0]), "r"(b[1]));
}
__device__ __forceinline__ void ldsm_x4(uint32_t* r, uint32_t addr) {
    asm volatile("ldmatrix.sync.aligned.m8n8.x4.shared.b16 {%0,%1,%2,%3}, [%4];"
        : "=r"(r[0]), "=r"(r[1]), "=r"(r[2]), "=r"(r[3]) : "r"(addr));
}

// ---------------------------------------------------------------------------
// n2[j] = ||negative_j||^2 exact fp32
__global__ void n2_kernel(const float* __restrict__ B) {
    int row  = blockIdx.x * 8 + (threadIdx.x >> 5);
    int lane = threadIdx.x & 31;
    const float4* p = reinterpret_cast<const float4*>(B + (size_t)row * D);
    float s = 0.f;
#pragma unroll
    for (int it = 0; it < (D / 4) / 32; ++it) {
        float4 v = p[it * 32 + lane];
        s += v.x * v.x + v.y * v.y + v.z * v.z + v.w * v.w;
    }
#pragma unroll
    for (int off = 16; off > 0; off >>= 1) s += __shfl_xor_sync(0xFFFFFFFFu, s, off);
    if (lane == 0) g_n2[row] = s;
}

// fp32 -> bf16 (rn)
__global__ void cvt_kernel(const float* __restrict__ src, __nv_bfloat16* __restrict__ dst) {
    size_t idx = ((size_t)blockIdx.x * 256 + threadIdx.x) * 4;
    float4 v = *reinterpret_cast<const float4*>(src + idx);
    __nv_bfloat162 lo = __floats2bfloat162_rn(v.x, v.y);
    __nv_bfloat162 hi = __floats2bfloat162_rn(v.z, v.w);
    uint2 o = make_uint2(*reinterpret_cast<uint32_t*>(&lo), *reinterpret_cast<uint32_t*>(&hi));
    *reinterpret_cast<uint2*>(dst + idx) = o;
}

// ---------------------------------------------------------------------------
// Phase 1: bf16 mma.sync GEMM (128x128, K=1024), BK=64, 3-stage cp.async,
// XOR-swizzled smem (128 B rows), ldmatrix fragments.
// score = n2[j] - 2*dot -> fp16 g_S + per-(row,tile) fp32 max.
// ---------------------------------------------------------------------------
#define STG_BYTES (128 * 128)                 // 16384 per matrix per stage
#define SM_B_OFF  (STAGES * STG_BYTES)        // 49152
#define SM_N2_OFF (2 * STAGES * STG_BYTES)    // 98304
#define SM_TM_OFF (SM_N2_OFF + 512)
#define SM_TOTAL  (SM_TM_OFF + 2048)          // 100864

__global__ void __launch_bounds__(256, 2)
gemm_kernel() {
    extern __shared__ __align__(16) char sm[];
    const uint32_t sb = smem_u32(sm);
    const int tid  = threadIdx.x;
    const int lane = tid & 31;
    const int wid  = tid >> 5;
    const int wm   = wid >> 2;       // 0..1
    const int wn   = wid & 3;        // 0..3
    const int g    = lane >> 2;      // 0..7
    const int tig  = lane & 3;       // 0..3

    const int it = blockIdx.x, jt = blockIdx.y;
    const int i0 = it * BM, j0 = jt * BN;

    float* n2s   = reinterpret_cast<float*>(sm + SM_N2_OFF);
    float* tmaxs = reinterpret_cast<float*>(sm + SM_TM_OFF);
    if (tid < BN) n2s[tid] = g_n2[j0 + tid];

    // gmem->smem loader: 8 threads per 128-B row, 4 row-waves per matrix
    const int lr   = tid >> 3;             // 0..31
    const int lc16 = tid & 7;              // 16B-chunk col 0..7

    const __nv_bfloat16* Ag = g_Ah + (size_t)i0 * D;
    const __nv_bfloat16* Bg = g_Bh + (size_t)j0 * D;

    auto issue = [&](int c) {
        const int st = ((unsigned)c) % STAGES;
        uint32_t sa  = sb + st * STG_BYTES;
        uint32_t sbb = sb + SM_B_OFF + st * STG_BYTES;
        const char* ag = reinterpret_cast<const char*>(Ag + c * BK);
        const char* bg = reinterpret_cast<const char*>(Bg + c * BK);
#pragma unroll
        for (int v = 0; v < 4; ++v) {
            int r = lr + v * 32;
            uint32_t soff = (uint32_t)(r * 128 + ((lc16 ^ (r & 7)) * 16));
            cp_async16(sa  + soff, ag + (size_t)r * (D * 2) + lc16 * 16);
            cp_async16(sbb + soff, bg + (size_t)r * (D * 2) + lc16 * 16);
        }
        CP_COMMIT();
    };

    issue(0);
    issue(1);

    // ldmatrix per-lane constants (q = lane>>3 selects the 8x8 sub-matrix)
    const int q  = lane >> 3;
    const int r8 = lane & 7;
    const uint32_t arow = (uint32_t)(((q & 1) * 8 + r8) * 128);  // within warp's A rows
    const int acol = q >> 1;                                      // 0/1 (16B units)
    const uint32_t brow = (uint32_t)(((q >> 1) * 8 + r8) * 128);
    const int bcol = q & 1;

    float acc[4][4][4];
#pragma unroll
    for (int m = 0; m < 4; ++m)
#pragma unroll
        for (int n = 0; n < 4; ++n)
#pragma unroll
            for (int qq = 0; qq < 4; ++qq) acc[m][n][qq] = 0.f;

    const int NCH = D / BK;   // 16
    for (int c = 0; c < NCH; ++c) {
        const int st = ((unsigned)c) % STAGES;
        if (c == NCH - 1) CP_WAIT(0); else CP_WAIT(1);
        __syncthreads();
        if (c + 2 < NCH) issue(c + 2);   // lands 2 compute-blocks ahead

        const uint32_t sA = sb + st * STG_BYTES + (uint32_t)((wm * 64) * 128);
        const uint32_t sB = sb + SM_B_OFF + st * STG_BYTES + (uint32_t)((wn * 32) * 128);
#pragma unroll
        for (int ks = 0; ks < BK / 16; ++ks) {      // 4 independent k-slices
            uint32_t a[4][4], b[4][2];
#pragma unroll
            for (int mt = 0; mt < 4; ++mt)
                ldsm_x4(a[mt], sA + (uint32_t)(mt * 16 * 128) + arow
                               + (uint32_t)((((ks * 2 + acol) ^ r8) & 7) * 16)
                               + (uint32_t)(((ks * 2 + acol) & ~7) * 16));
#pragma unroll
            for (int p = 0; p < 2; ++p) {
                uint32_t bp[4];
                ldsm_x4(bp, sB + (uint32_t)(p * 16 * 128) + brow
                            + (uint32_t)((((ks * 2 + bcol) ^ r8) & 7) * 16)
                            + (uint32_t)(((ks * 2 + bcol) & ~7) * 16));
                b[2 * p][0]     = bp[0];
                b[2 * p][1]     = bp[1];
                b[2 * p + 1][0] = bp[2];
                b[2 * p + 1][1] = bp[3];
            }
#pragma unroll
            for (int mt = 0; mt < 4; ++mt)
#pragma unroll
                for (int nt = 0; nt < 4; ++nt)
                    mma_bf16(acc[mt][nt], a[mt], b[nt]);
        }
    }

    // Epilogue: scores, fp16 store, per-row max
    __syncthreads();
    float rmax[8];
#pragma unroll
    for (int qq = 0; qq < 8; ++qq) rmax[qq] = -FLT_MAX;

#pragma unroll
    for (int mt = 0; mt < 4; ++mt) {
        const int r0 = wm * 64 + mt * 16 + g;
        const int r1 = r0 + 8;
#pragma unroll
        for (int nt = 0; nt < 4; ++nt) {
            const int c0 = wn * 32 + nt * 8 + tig * 2;
            float s00 = n2s[c0]     - 2.f * acc[mt][nt][0];
            float s01 = n2s[c0 + 1] - 2.f * acc[mt][nt][1];
            float s10 = n2s[c0]     - 2.f * acc[mt][nt][2];
            float s11 = n2s[c0 + 1] - 2.f * acc[mt][nt][3];
            *reinterpret_cast<__half2*>(&g_S[(size_t)(i0 + r0) * N + j0 + c0]) =
                __floats2half2_rn(s00, s01);
            *reinterpret_cast<__half2*>(&g_S[(size_t)(i0 + r1) * N + j0 + c0]) =
                __floats2half2_rn(s10, s11);
            rmax[mt * 2]     = fmaxf(rmax[mt * 2],     fmaxf(s00, s01));
            rmax[mt * 2 + 1] = fmaxf(rmax[mt * 2 + 1], fmaxf(s10, s11));
        }
    }
#pragma unroll
    for (int qq = 0; qq < 8; ++qq) {
        rmax[qq] = fmaxf(rmax[qq], __shfl_xor_sync(0xFFFFFFFFu, rmax[qq], 1));
        rmax[qq] = fmaxf(rmax[qq], __shfl_xor_sync(0xFFFFFFFFu, rmax[qq], 2));
    }
    if (tig == 0) {
#pragma unroll
        for (int mt = 0; mt < 4; ++mt) {
            tmaxs[(wm * 64 + mt * 16 + g) * 4 + wn]     = rmax[mt * 2];
            tmaxs[(wm * 64 + mt * 16 + g + 8) * 4 + wn] = rmax[mt * 2 + 1];
        }
    }
    __syncthreads();
    if (tid < BM) {
        float m = fmaxf(fmaxf(tmaxs[tid * 4 + 0], tmaxs[tid * 4 + 1]),
                        fmaxf(tmaxs[tid * 4 + 2], tmaxs[tid * 4 + 3]));
        g_tmax[(size_t)(i0 + tid) * NJT + jt] = m;
    }
}

// ---------------------------------------------------------------------------
__global__ void rowmax_kernel() {
    int row  = blockIdx.x * 8 + (threadIdx.x >> 5);
    int lane = threadIdx.x & 31;
    float m = fmaxf(g_tmax[(size_t)row * NJT + lane],
                    g_tmax[(size_t)row * NJT + 32 + lane]);
#pragma unroll
    for (int off = 16; off > 0; off >>= 1)
        m = fmaxf(m, __shfl_xor_sync(0xFFFFFFFFu, m, off));
    if (lane == 0) g_rowmax[row] = m;
}

// ---------------------------------------------------------------------------
// Phase 3: per-row candidate scan + exact fp32 rescore + gather. 1 CTA/row.
// ---------------------------------------------------------------------------
__global__ void __launch_bounds__(256)
select_kernel(const float* __restrict__ A, const float* __restrict__ B,
              float* __restrict__ out) {
    const int i = blockIdx.x;
    const int tid = threadIdx.x, lane = tid & 31, wid = tid >> 5;

    __shared__ int   cnt;
    __shared__ int   cand[MAXC];
    __shared__ float wred[8];
    __shared__ int   bestj_s;

    const float thresh = g_rowmax[i] - EPS;
    const float4 a4 = reinterpret_cast<const float4*>(A + (size_t)i * D)[tid];

    if (tid == 0) cnt = 0;
    __syncthreads();

    const __half* srow = g_S + (size_t)i * N;
    for (int j = tid; j < N; j += 256) {
        if (__half2float(srow[j]) > thresh) {
            int p = atomicAdd(&cnt, 1);
            if (p < MAXC) cand[p] = j;
        }
    }
    __syncthreads();
    const int nc = min(cnt, MAXC);

    float bestv = -FLT_MAX;
    int   bestj = 0x7fffffff;
    for (int c = 0; c < nc; ++c) {
        const int j = cand[c];
        const float4 b4 = reinterpret_cast<const float4*>(B + (size_t)j * D)[tid];
        float p = a4.x * b4.x + a4.y * b4.y + a4.z * b4.z + a4.w * b4.w;
#pragma unroll
        for (int off = 16; off > 0; off >>= 1) p += __shfl_xor_sync(0xFFFFFFFFu, p, off);
        if (lane == 0) wred[wid] = p;
        __syncthreads();
        if (tid == 0) {
            float dot = wred[0] + wred[1] + wred[2] + wred[3]
                      + wred[4] + wred[5] + wred[6] + wred[7];
            float sc = g_n2[j] - 2.f * dot;
            if (sc > bestv || (sc == bestv && j < bestj)) { bestv = sc; bestj = j; }
        }
        __syncthreads();
    }
    if (tid == 0) bestj_s = bestj;
    __syncthreads();

    const int j = bestj_s;
    reinterpret_cast<float4*>(out + (size_t)i * D)[tid] =
        reinterpret_cast<const float4*>(B + (size_t)j * D)[tid];
}

// ---------------------------------------------------------------------------
extern "C" void kernel_launch(void* const* d_in, const int* in_sizes, int n_in,
                              void* d_out, int out_size) {
    const float* anchor   = (const float*)d_in[0];
    const float* negative = (const float*)d_in[1];
    float* out = (float*)d_out;

    static __nv_bfloat16* s_Ah = nullptr;
    static __nv_bfloat16* s_Bh = nullptr;
    if (!s_Ah) { cudaGetSymbolAddress((void**)&s_Ah, g_Ah);
                 cudaGetSymbolAddress((void**)&s_Bh, g_Bh); }

    cudaFuncSetAttribute(gemm_kernel,
                         cudaFuncAttributeMaxDynamicSharedMemorySize, SM_TOTAL);

    n2_kernel<<<N / 8, 256>>>(negative);
    cvt_kernel<<<(int)(((size_t)N * D) / 1024), 256>>>(anchor,   s_Ah);
    cvt_kernel<<<(int)(((size_t)N * D) / 1024), 256>>>(negative, s_Bh);
    gemm_kernel<<<dim3(N / BM, N / BN), 256, SM_TOTAL>>>();
    rowmax_kernel<<<N / 8, 256>>>();
    select_kernel<<<N, 256>>>(anchor, negative, out);
}